// round 8
// baseline (speedup 1.0000x reference)
#include <cuda_runtime.h>
#include <cuda_bf16.h>
#include <stdint.h>

// Problem constants
#define Bd   2
#define Nseq 2048
#define Dm   1024
#define Hh   16
#define HD   64
#define SCALE 0.125f
#define Kdim 1024

// ---------------- device scratch (no allocations allowed) -------------------
__device__ __nv_bfloat16 g_xh[Bd*Nseq*Dm],  g_xl[Bd*Nseq*Dm];    // x split
__device__ __nv_bfloat16 g_wqh[3*Dm*Kdim],  g_wql[3*Dm*Kdim];    // w_qkv^T split [3072,1024]
__device__ __nv_bfloat16 g_wph[Dm*Kdim],    g_wpl[Dm*Kdim];      // w_proj^T split [1024,1024]
__device__ __nv_bfloat16 g_qh[Bd*Hh*Nseq*HD], g_ql[Bd*Hh*Nseq*HD]; // q*scale split [B,H,N,64]
__device__ __nv_bfloat16 g_kh[Bd*Hh*Nseq*HD], g_kl[Bd*Hh*Nseq*HD];
__device__ __nv_bfloat16 g_vh[Bd*Hh*Nseq*HD], g_vl[Bd*Hh*Nseq*HD];
__device__ __nv_bfloat16 g_ah[Bd*Nseq*Dm],  g_al[Bd*Nseq*Dm];    // attention out split

// ---------------- helpers ----------------------------------------------------
__device__ __forceinline__ uint32_t smem_u32(const void* p) {
    return (uint32_t)__cvta_generic_to_shared(p);
}
__device__ __forceinline__ void mma_bf16(float (&d)[4], const uint32_t (&a)[4],
                                         const uint32_t (&b)[2]) {
    asm volatile(
        "mma.sync.aligned.m16n8k16.row.col.f32.bf16.bf16.f32 "
        "{%0,%1,%2,%3}, {%4,%5,%6,%7}, {%8,%9}, {%0,%1,%2,%3};"
        : "+f"(d[0]), "+f"(d[1]), "+f"(d[2]), "+f"(d[3])
        : "r"(a[0]), "r"(a[1]), "r"(a[2]), "r"(a[3]), "r"(b[0]), "r"(b[1]));
}
__device__ __forceinline__ void ldsm4(uint32_t (&r)[4], uint32_t addr) {
    asm volatile("ldmatrix.sync.aligned.m8n8.x4.shared.b16 {%0,%1,%2,%3}, [%4];"
        : "=r"(r[0]), "=r"(r[1]), "=r"(r[2]), "=r"(r[3]) : "r"(addr));
}
__device__ __forceinline__ void ldsm4t(uint32_t (&r)[4], uint32_t addr) {
    asm volatile("ldmatrix.sync.aligned.m8n8.x4.trans.shared.b16 {%0,%1,%2,%3}, [%4];"
        : "=r"(r[0]), "=r"(r[1]), "=r"(r[2]), "=r"(r[3]) : "r"(addr));
}
__device__ __forceinline__ uint32_t pack_bf16(float lo, float hi) {
    uint32_t r;
    asm("cvt.rn.bf16x2.f32 %0, %1, %2;" : "=r"(r) : "f"(hi), "f"(lo));
    return r;
}
__device__ __forceinline__ void cp16(uint32_t s, const void* g) {
    asm volatile("cp.async.cg.shared.global [%0], [%1], 16;" :: "r"(s), "l"(g));
}
#define CP_COMMIT() asm volatile("cp.async.commit_group;" ::: "memory")
#define CP_WAIT1()  asm volatile("cp.async.wait_group 1;" ::: "memory")
#define CP_WAIT0()  asm volatile("cp.async.wait_group 0;" ::: "memory")

// ---------------- split/transpose pre-passes --------------------------------
__global__ void __launch_bounds__(256) conv_x_kernel(const float* __restrict__ x) {
    int i4 = (blockIdx.x * 256 + threadIdx.x) * 4;
    if (i4 >= Bd * Nseq * Dm) return;
    float4 v = *(const float4*)&x[i4];
    __nv_bfloat16 hx = __float2bfloat16(v.x), hy = __float2bfloat16(v.y);
    __nv_bfloat16 hz = __float2bfloat16(v.z), hw = __float2bfloat16(v.w);
    *(__nv_bfloat162*)&g_xh[i4]     = __nv_bfloat162(hx, hy);
    *(__nv_bfloat162*)&g_xh[i4 + 2] = __nv_bfloat162(hz, hw);
    *(__nv_bfloat162*)&g_xl[i4]     = __nv_bfloat162(
        __float2bfloat16(v.x - __bfloat162float(hx)),
        __float2bfloat16(v.y - __bfloat162float(hy)));
    *(__nv_bfloat162*)&g_xl[i4 + 2] = __nv_bfloat162(
        __float2bfloat16(v.z - __bfloat162float(hz)),
        __float2bfloat16(v.w - __bfloat162float(hw)));
}

template<int WHICH>  // 0: qkv, 1: proj
__global__ void __launch_bounds__(256) convT_kernel(const float* __restrict__ w, int N) {
    __shared__ float t[32][33];
    int tx = threadIdx.x & 31, ty = threadIdx.x >> 5;   // 32 x 8
    int n0 = blockIdx.x * 32, k0 = blockIdx.y * 32;
    #pragma unroll
    for (int i = 0; i < 4; i++) {
        int k = k0 + ty + i * 8;
        t[ty + i * 8][tx] = w[(size_t)k * N + n0 + tx];
    }
    __syncthreads();
    __nv_bfloat16* dh = WHICH ? g_wph : g_wqh;
    __nv_bfloat16* dl = WHICH ? g_wpl : g_wql;
    #pragma unroll
    for (int i = 0; i < 4; i++) {
        int n = n0 + ty + i * 8;
        float v = t[tx][ty + i * 8];
        __nv_bfloat16 h = __float2bfloat16(v);
        dh[(size_t)n * Kdim + k0 + tx] = h;
        dl[(size_t)n * Kdim + k0 + tx] = __float2bfloat16(v - __bfloat162float(h));
    }
}

// ---------------- HMMA GEMM: cp.async 3-stage, 128x128 tile -----------------
// 256 threads, 8 warps (2m x 4n), warp tile 64x32, K-tile 32.
// Stage layout (40960 B): Ah[128*80] Al[128*80] Bh[128*80] Bl[128*80]
#define GSTAGE 40960
#define GEMM_DSMEM (3 * GSTAGE)
#define GEMM_NT (Kdim / 32)

template<int MODE>
__global__ void __launch_bounds__(256) mma_gemm(const float* __restrict__ bias,
                                                float* __restrict__ C, int Nc) {
    extern __shared__ char dyn[];
    const uint32_t sbase = smem_u32(dyn);

    const int tid = threadIdx.x, lane = tid & 31, wid = tid >> 5;
    const int m0 = blockIdx.y * 128, n0 = blockIdx.x * 128;
    const __nv_bfloat16* Ah = MODE ? g_xh  : g_ah;
    const __nv_bfloat16* Al = MODE ? g_xl  : g_al;
    const __nv_bfloat16* Bh = MODE ? g_wqh : g_wph;
    const __nv_bfloat16* Bl = MODE ? g_wql : g_wpl;
    const int wm = (wid >> 2) * 64, wn = (wid & 3) * 32;

    float acc[4][4][4] = {};

    const uint32_t lmr = (uint32_t)(lane & 15);
    const uint32_t lmc = (uint32_t)((lane >> 4) * 16);
    const int fr = tid >> 2, fc = tid & 3;   // fill: row base, 16B chunk

    // fill stage st with K-tile at k0
    auto fill = [&](int st, int k0) {
        uint32_t sb = sbase + st * GSTAGE;
        uint32_t off = (uint32_t)(fr * 80 + fc * 16);
        #pragma unroll
        for (int half = 0; half < 2; half++) {
            int r = fr + half * 64;
            uint32_t o = off + half * 64 * 80;
            size_t ga = (size_t)(m0 + r) * Kdim + k0 + fc * 8;
            size_t gb = (size_t)(n0 + r) * Kdim + k0 + fc * 8;
            cp16(sb + o,              &Ah[ga]);
            cp16(sb + 10240 + o,      &Al[ga]);
            cp16(sb + 20480 + o,      &Bh[gb]);
            cp16(sb + 30720 + o,      &Bl[gb]);
        }
    };

    fill(0, 0);  CP_COMMIT();
    fill(1, 32); CP_COMMIT();

    for (int t = 0; t < GEMM_NT; t++) {
        if (t + 2 < GEMM_NT) CP_WAIT1(); else CP_WAIT0();
        __syncthreads();
        if (t + 2 < GEMM_NT) { fill((t + 2) % 3, (t + 2) * 32); CP_COMMIT(); }

        const uint32_t sb = sbase + (t % 3) * GSTAGE;
        const uint32_t aAh = sb, aAl = sb + 10240, aBh = sb + 20480, aBl = sb + 30720;

        #pragma unroll
        for (int kt = 0; kt < 2; kt++) {
            uint32_t ah[4][4], al[4][4], bh[4][2], bl[4][2];
            #pragma unroll
            for (int mi = 0; mi < 4; mi++) {
                uint32_t ro = (wm + mi * 16 + lmr) * 80 + kt * 32 + lmc;
                ldsm4(ah[mi], aAh + ro);
                ldsm4(al[mi], aAl + ro);
            }
            #pragma unroll
            for (int g = 0; g < 2; g++) {
                uint32_t ro = (wn + g * 16 + lmr) * 80 + kt * 32 + lmc;
                uint32_t tt[4];
                ldsm4(tt, aBh + ro);
                bh[2*g][0] = tt[0]; bh[2*g][1] = tt[2];
                bh[2*g+1][0] = tt[1]; bh[2*g+1][1] = tt[3];
                ldsm4(tt, aBl + ro);
                bl[2*g][0] = tt[0]; bl[2*g][1] = tt[2];
                bl[2*g+1][0] = tt[1]; bl[2*g+1][1] = tt[3];
            }
            #pragma unroll
            for (int mi = 0; mi < 4; mi++)
                #pragma unroll
                for (int ni = 0; ni < 4; ni++) {
                    mma_bf16(acc[mi][ni], ah[mi], bh[ni]);
                    mma_bf16(acc[mi][ni], ah[mi], bl[ni]);
                    mma_bf16(acc[mi][ni], al[mi], bh[ni]);
                }
        }
    }

    // epilogue
    #pragma unroll
    for (int mi = 0; mi < 4; mi++) {
        int r0 = m0 + wm + mi * 16 + (lane >> 2);
        #pragma unroll
        for (int ni = 0; ni < 4; ni++) {
            int col = n0 + wn + ni * 8 + 2 * (lane & 3);
            float b0 = bias[col], b1 = bias[col + 1];
            #pragma unroll
            for (int rr = 0; rr < 2; rr++) {
                int row = r0 + rr * 8;
                float v0 = acc[mi][ni][rr * 2 + 0] + b0;
                float v1 = acc[mi][ni][rr * 2 + 1] + b1;
                if (MODE == 0) {
                    *(float2*)&C[(size_t)row * Nc + col] = make_float2(v0, v1);
                } else {
                    int bb = row >> 11, nn = row & 2047;
                    int which = col >> 10, rem = col & 1023;
                    int hh = rem >> 6, dd = rem & 63;
                    if (which == 0) { v0 *= SCALE; v1 *= SCALE; }
                    __nv_bfloat16 h0 = __float2bfloat16(v0), h1 = __float2bfloat16(v1);
                    __nv_bfloat16 l0 = __float2bfloat16(v0 - __bfloat162float(h0));
                    __nv_bfloat16 l1 = __float2bfloat16(v1 - __bfloat162float(h1));
                    size_t idx = (((size_t)(bb * Hh + hh)) * Nseq + nn) * HD + dd;
                    __nv_bfloat16* dh = (which == 0) ? g_qh : (which == 1) ? g_kh : g_vh;
                    __nv_bfloat16* dl = (which == 0) ? g_ql : (which == 1) ? g_kl : g_vl;
                    *(__nv_bfloat162*)&dh[idx] = __nv_bfloat162(h0, h1);
                    *(__nv_bfloat162*)&dl[idx] = __nv_bfloat162(l0, l1);
                }
            }
        }
    }
}

// ---------------- flash attention: cp.async 3-stage --------------------------
// 8 warps, Q-tile 128 (Q in registers), K-tile 64.
// Stage (36864 B): Kh[64*144B] Kl Vh Vl ; bias after stages: 3*256 B
#define FSTAGE 36864
#define FLASH_DSMEM (3 * FSTAGE + 3 * 256)
#define FLASH_NT (Nseq / 64)

__global__ void __launch_bounds__(256) flash_mma(const float* __restrict__ attn_bias) {
    extern __shared__ char dyn[];
    const uint32_t sbase = smem_u32(dyn);
    const uint32_t sbias = sbase + 3 * FSTAGE;

    const int tid = threadIdx.x, lane = tid & 31, wid = tid >> 5;
    const int b = blockIdx.z, h = blockIdx.y, q0 = blockIdx.x * 128;
    const size_t hoff = (size_t)((b * Hh + h) * Nseq) * HD;
    const __nv_bfloat16 *Qhp = g_qh + hoff, *Qlp = g_ql + hoff;
    const __nv_bfloat16 *Khp = g_kh + hoff, *Klp = g_kl + hoff;
    const __nv_bfloat16 *Vhp = g_vh + hoff, *Vlp = g_vl + hoff;
    const float* biasg = attn_bias + b * Nseq;

    const int fr = tid >> 3, fc = tid & 7;   // fill: row base (0..31), 16B chunk (0..7)

    auto fill = [&](int st, int k0) {
        uint32_t sb = sbase + st * FSTAGE;
        #pragma unroll
        for (int half = 0; half < 2; half++) {
            int r = fr + half * 32;
            uint32_t o = (uint32_t)(r * 144 + fc * 16);
            size_t g = (size_t)(k0 + r) * HD + fc * 8;
            cp16(sb + o,             &Khp[g]);
            cp16(sb + 9216 + o,      &Klp[g]);
            cp16(sb + 18432 + o,     &Vhp[g]);
            cp16(sb + 27648 + o,     &Vlp[g]);
        }
        if (tid < 16) cp16(sbias + st * 256 + tid * 16, &biasg[k0 + tid * 4]);
    };

    // ---- Q A-fragments directly from gmem ----
    uint32_t qh[4][4], ql[4][4];
    {
        int r = q0 + wid * 16 + (lane >> 2);
        int c = 2 * (lane & 3);
        #pragma unroll
        for (int kf = 0; kf < 4; kf++) {
            #pragma unroll
            for (int e = 0; e < 4; e++) {
                size_t g = (size_t)(r + (e & 1) * 8) * HD + kf * 16 + (e >> 1) * 8 + c;
                qh[kf][e] = *(const uint32_t*)&Qhp[g];
                ql[kf][e] = *(const uint32_t*)&Qlp[g];
            }
        }
    }

    fill(0, 0);  CP_COMMIT();
    fill(1, 64); CP_COMMIT();

    float O[8][4] = {};
    float mrow0 = -1e30f, mrow1 = -1e30f, lrow0 = 0.f, lrow1 = 0.f;

    for (int t = 0; t < FLASH_NT; t++) {
        if (t + 2 < FLASH_NT) CP_WAIT1(); else CP_WAIT0();
        __syncthreads();
        if (t + 2 < FLASH_NT) { fill((t + 2) % 3, (t + 2) * 64); CP_COMMIT(); }

        const uint32_t sb = sbase + (t % 3) * FSTAGE;
        const uint32_t aKh = sb, aKl = sb + 9216, aVh = sb + 18432, aVl = sb + 27648;
        const float* sB = (const float*)(dyn + 3 * FSTAGE + (t % 3) * 256);

        // ---- S = Q K^T ----
        float S[8][4] = {};
        #pragma unroll
        for (int kf = 0; kf < 4; kf++) {
            #pragma unroll
            for (int g = 0; g < 4; g++) {
                uint32_t ro = (uint32_t)((g * 16 + (lane & 15)) * 144 + kf * 32 + (lane >> 4) * 16);
                uint32_t tt[4], bh0[2], bh1[2], bl0[2], bl1[2];
                ldsm4(tt, aKh + ro);
                bh0[0] = tt[0]; bh0[1] = tt[2]; bh1[0] = tt[1]; bh1[1] = tt[3];
                ldsm4(tt, aKl + ro);
                bl0[0] = tt[0]; bl0[1] = tt[2]; bl1[0] = tt[1]; bl1[1] = tt[3];
                mma_bf16(S[2*g],   qh[kf], bh0);
                mma_bf16(S[2*g],   qh[kf], bl0);
                mma_bf16(S[2*g],   ql[kf], bh0);
                mma_bf16(S[2*g+1], qh[kf], bh1);
                mma_bf16(S[2*g+1], qh[kf], bl1);
                mma_bf16(S[2*g+1], ql[kf], bh1);
            }
        }

        // ---- bias + online softmax ----
        float mx0 = mrow0, mx1 = mrow1;
        #pragma unroll
        for (int nt = 0; nt < 8; nt++) {
            float2 bb = *(const float2*)&sB[nt * 8 + 2 * (lane & 3)];
            S[nt][0] += bb.x; S[nt][1] += bb.y;
            S[nt][2] += bb.x; S[nt][3] += bb.y;
            mx0 = fmaxf(mx0, fmaxf(S[nt][0], S[nt][1]));
            mx1 = fmaxf(mx1, fmaxf(S[nt][2], S[nt][3]));
        }
        mx0 = fmaxf(mx0, __shfl_xor_sync(0xffffffffu, mx0, 1));
        mx0 = fmaxf(mx0, __shfl_xor_sync(0xffffffffu, mx0, 2));
        mx1 = fmaxf(mx1, __shfl_xor_sync(0xffffffffu, mx1, 1));
        mx1 = fmaxf(mx1, __shfl_xor_sync(0xffffffffu, mx1, 2));
        float alpha0 = __expf(mrow0 - mx0), alpha1 = __expf(mrow1 - mx1);
        mrow0 = mx0; mrow1 = mx1;
        float sum0 = 0.f, sum1 = 0.f;
        #pragma unroll
        for (int nt = 0; nt < 8; nt++) {
            S[nt][0] = __expf(S[nt][0] - mx0); S[nt][1] = __expf(S[nt][1] - mx0);
            S[nt][2] = __expf(S[nt][2] - mx1); S[nt][3] = __expf(S[nt][3] - mx1);
            sum0 += S[nt][0] + S[nt][1];
            sum1 += S[nt][2] + S[nt][3];
        }
        sum0 += __shfl_xor_sync(0xffffffffu, sum0, 1);
        sum0 += __shfl_xor_sync(0xffffffffu, sum0, 2);
        sum1 += __shfl_xor_sync(0xffffffffu, sum1, 1);
        sum1 += __shfl_xor_sync(0xffffffffu, sum1, 2);
        lrow0 = lrow0 * alpha0 + sum0;
        lrow1 = lrow1 * alpha1 + sum1;
        #pragma unroll
        for (int dt = 0; dt < 8; dt++) {
            O[dt][0] *= alpha0; O[dt][1] *= alpha0;
            O[dt][2] *= alpha1; O[dt][3] *= alpha1;
        }

        // ---- P -> A-fragments (hi/lo split) ----
        uint32_t pah[4][4], pal[4][4];
        #pragma unroll
        for (int kt = 0; kt < 4; kt++) {
            #pragma unroll
            for (int half = 0; half < 2; half++) {
                int nt = 2 * kt + half;
                float p0 = S[nt][0], p1 = S[nt][1], p2 = S[nt][2], p3 = S[nt][3];
                __nv_bfloat16 h0 = __float2bfloat16(p0), h1 = __float2bfloat16(p1);
                __nv_bfloat16 h2 = __float2bfloat16(p2), h3 = __float2bfloat16(p3);
                pah[kt][half * 2 + 0] = pack_bf16(__bfloat162float(h0), __bfloat162float(h1));
                pah[kt][half * 2 + 1] = pack_bf16(__bfloat162float(h2), __bfloat162float(h3));
                pal[kt][half * 2 + 0] = pack_bf16(p0 - __bfloat162float(h0), p1 - __bfloat162float(h1));
                pal[kt][half * 2 + 1] = pack_bf16(p2 - __bfloat162float(h2), p3 - __bfloat162float(h3));
            }
        }

        // ---- O += P V ----
        #pragma unroll
        for (int kt = 0; kt < 4; kt++) {
            #pragma unroll
            for (int g = 0; g < 4; g++) {
                uint32_t ro = (uint32_t)((kt * 16 + (lane & 7) + 8 * ((lane >> 3) & 1)) * 144
                                         + g * 32 + (lane >> 4) * 16);
                uint32_t tt[4], vh0[2], vh1[2], vl0[2], vl1[2];
                ldsm4t(tt, aVh + ro);
                vh0[0] = tt[0]; vh0[1] = tt[1]; vh1[0] = tt[2]; vh1[1] = tt[3];
                ldsm4t(tt, aVl + ro);
                vl0[0] = tt[0]; vl0[1] = tt[1]; vl1[0] = tt[2]; vl1[1] = tt[3];
                mma_bf16(O[2*g],   pah[kt], vh0);
                mma_bf16(O[2*g],   pah[kt], vl0);
                mma_bf16(O[2*g],   pal[kt], vh0);
                mma_bf16(O[2*g+1], pah[kt], vh1);
                mma_bf16(O[2*g+1], pah[kt], vl1);
                mma_bf16(O[2*g+1], pal[kt], vh1);
            }
        }
    }

    // ---- epilogue ----
    float inv0 = 1.f / lrow0, inv1 = 1.f / lrow1;
    int r0 = q0 + wid * 16 + (lane >> 2);
    #pragma unroll
    for (int dt = 0; dt < 8; dt++) {
        int col = h * HD + dt * 8 + 2 * (lane & 3);
        float v00 = O[dt][0] * inv0, v01 = O[dt][1] * inv0;
        float v10 = O[dt][2] * inv1, v11 = O[dt][3] * inv1;
        size_t i0 = (size_t)(b * Nseq + r0) * Dm + col;
        size_t i1 = (size_t)(b * Nseq + r0 + 8) * Dm + col;
        __nv_bfloat16 h00 = __float2bfloat16(v00), h01 = __float2bfloat16(v01);
        __nv_bfloat16 h10 = __float2bfloat16(v10), h11 = __float2bfloat16(v11);
        *(__nv_bfloat162*)&g_ah[i0] = __nv_bfloat162(h00, h01);
        *(__nv_bfloat162*)&g_ah[i1] = __nv_bfloat162(h10, h11);
        *(__nv_bfloat162*)&g_al[i0] = __nv_bfloat162(
            __float2bfloat16(v00 - __bfloat162float(h00)),
            __float2bfloat16(v01 - __bfloat162float(h01)));
        *(__nv_bfloat162*)&g_al[i1] = __nv_bfloat162(
            __float2bfloat16(v10 - __bfloat162float(h10)),
            __float2bfloat16(v11 - __bfloat162float(h11)));
    }
}

// ---------------- launch -----------------------------------------------------
extern "C" void kernel_launch(void* const* d_in, const int* in_sizes, int n_in,
                              void* d_out, int out_size)
{
    const float* x         = (const float*)d_in[0];
    const float* attn_bias = (const float*)d_in[1];
    const float* w_qkv     = (const float*)d_in[2];
    const float* b_qkv     = (const float*)d_in[3];
    const float* w_proj    = (const float*)d_in[4];
    const float* b_proj    = (const float*)d_in[5];
    float* out = (float*)d_out;

    cudaFuncSetAttribute(mma_gemm<1>, cudaFuncAttributeMaxDynamicSharedMemorySize, GEMM_DSMEM);
    cudaFuncSetAttribute(mma_gemm<0>, cudaFuncAttributeMaxDynamicSharedMemorySize, GEMM_DSMEM);
    cudaFuncSetAttribute(flash_mma,   cudaFuncAttributeMaxDynamicSharedMemorySize, FLASH_DSMEM);

    conv_x_kernel<<<(Bd * Nseq * Dm) / (256 * 4), 256>>>(x);
    convT_kernel<0><<<dim3(3 * Dm / 32, Kdim / 32), 256>>>(w_qkv, 3 * Dm);
    convT_kernel<1><<<dim3(Dm / 32, Kdim / 32), 256>>>(w_proj, Dm);

    mma_gemm<1><<<dim3(3 * Dm / 128, (Bd * Nseq) / 128), 256, GEMM_DSMEM>>>(b_qkv, nullptr, 3 * Dm);

    flash_mma<<<dim3(Nseq / 128, Hh, Bd), 256, FLASH_DSMEM>>>(attn_bias);

    mma_gemm<0><<<dim3(Dm / 128, (Bd * Nseq) / 128), 256, GEMM_DSMEM>>>(b_proj, out, Dm);
}

// round 9
// speedup vs baseline: 1.0008x; 1.0008x over previous
#include <cuda_runtime.h>
#include <cuda_bf16.h>
#include <stdint.h>

// Problem constants
#define Bd   2
#define Nseq 2048
#define Dm   1024
#define Hh   16
#define HD   64
#define SCALE 0.125f
#define Kdim 1024

// ---------------- device scratch (no allocations allowed) -------------------
__device__ __nv_bfloat16 g_xh[Bd*Nseq*Dm],  g_xl[Bd*Nseq*Dm];    // x split
__device__ __nv_bfloat16 g_wqh[3*Dm*Kdim],  g_wql[3*Dm*Kdim];    // w_qkv^T split [3072,1024]
__device__ __nv_bfloat16 g_wph[Dm*Kdim],    g_wpl[Dm*Kdim];      // w_proj^T split [1024,1024]
__device__ __nv_bfloat16 g_qh[Bd*Hh*Nseq*HD], g_ql[Bd*Hh*Nseq*HD]; // q*scale split [B,H,N,64]
__device__ __nv_bfloat16 g_kh[Bd*Hh*Nseq*HD], g_kl[Bd*Hh*Nseq*HD];
__device__ __nv_bfloat16 g_vh[Bd*Hh*Nseq*HD], g_vl[Bd*Hh*Nseq*HD];
__device__ __nv_bfloat16 g_ah[Bd*Nseq*Dm],  g_al[Bd*Nseq*Dm];    // attention out split

// ---------------- helpers ----------------------------------------------------
__device__ __forceinline__ uint32_t smem_u32(const void* p) {
    return (uint32_t)__cvta_generic_to_shared(p);
}
__device__ __forceinline__ void mma_bf16(float (&d)[4], const uint32_t (&a)[4],
                                         const uint32_t (&b)[2]) {
    asm volatile(
        "mma.sync.aligned.m16n8k16.row.col.f32.bf16.bf16.f32 "
        "{%0,%1,%2,%3}, {%4,%5,%6,%7}, {%8,%9}, {%0,%1,%2,%3};"
        : "+f"(d[0]), "+f"(d[1]), "+f"(d[2]), "+f"(d[3])
        : "r"(a[0]), "r"(a[1]), "r"(a[2]), "r"(a[3]), "r"(b[0]), "r"(b[1]));
}
__device__ __forceinline__ void ldsm4(uint32_t (&r)[4], uint32_t addr) {
    asm volatile("ldmatrix.sync.aligned.m8n8.x4.shared.b16 {%0,%1,%2,%3}, [%4];"
        : "=r"(r[0]), "=r"(r[1]), "=r"(r[2]), "=r"(r[3]) : "r"(addr));
}
__device__ __forceinline__ void ldsm4t(uint32_t (&r)[4], uint32_t addr) {
    asm volatile("ldmatrix.sync.aligned.m8n8.x4.trans.shared.b16 {%0,%1,%2,%3}, [%4];"
        : "=r"(r[0]), "=r"(r[1]), "=r"(r[2]), "=r"(r[3]) : "r"(addr));
}
__device__ __forceinline__ uint32_t pack_bf16(float lo, float hi) {
    uint32_t r;
    asm("cvt.rn.bf16x2.f32 %0, %1, %2;" : "=r"(r) : "f"(hi), "f"(lo));
    return r;
}
__device__ __forceinline__ void cp16(uint32_t s, const void* g) {
    asm volatile("cp.async.cg.shared.global [%0], [%1], 16;" :: "r"(s), "l"(g));
}
#define CP_COMMIT() asm volatile("cp.async.commit_group;" ::: "memory")
#define CP_WAIT1()  asm volatile("cp.async.wait_group 1;" ::: "memory")
#define CP_WAIT0()  asm volatile("cp.async.wait_group 0;" ::: "memory")

// ---------------- split/transpose pre-passes --------------------------------
__global__ void __launch_bounds__(256) conv_x_kernel(const float* __restrict__ x) {
    int i4 = (blockIdx.x * 256 + threadIdx.x) * 4;
    if (i4 >= Bd * Nseq * Dm) return;
    float4 v = *(const float4*)&x[i4];
    __nv_bfloat16 hx = __float2bfloat16(v.x), hy = __float2bfloat16(v.y);
    __nv_bfloat16 hz = __float2bfloat16(v.z), hw = __float2bfloat16(v.w);
    *(__nv_bfloat162*)&g_xh[i4]     = __nv_bfloat162(hx, hy);
    *(__nv_bfloat162*)&g_xh[i4 + 2] = __nv_bfloat162(hz, hw);
    *(__nv_bfloat162*)&g_xl[i4]     = __nv_bfloat162(
        __float2bfloat16(v.x - __bfloat162float(hx)),
        __float2bfloat16(v.y - __bfloat162float(hy)));
    *(__nv_bfloat162*)&g_xl[i4 + 2] = __nv_bfloat162(
        __float2bfloat16(v.z - __bfloat162float(hz)),
        __float2bfloat16(v.w - __bfloat162float(hw)));
}

template<int WHICH>  // 0: qkv, 1: proj
__global__ void __launch_bounds__(256) convT_kernel(const float* __restrict__ w, int N) {
    __shared__ float t[32][33];
    int tx = threadIdx.x & 31, ty = threadIdx.x >> 5;   // 32 x 8
    int n0 = blockIdx.x * 32, k0 = blockIdx.y * 32;
    #pragma unroll
    for (int i = 0; i < 4; i++) {
        int k = k0 + ty + i * 8;
        t[ty + i * 8][tx] = w[(size_t)k * N + n0 + tx];
    }
    __syncthreads();
    __nv_bfloat16* dh = WHICH ? g_wph : g_wqh;
    __nv_bfloat16* dl = WHICH ? g_wpl : g_wql;
    #pragma unroll
    for (int i = 0; i < 4; i++) {
        int n = n0 + ty + i * 8;
        float v = t[tx][ty + i * 8];
        __nv_bfloat16 h = __float2bfloat16(v);
        dh[(size_t)n * Kdim + k0 + tx] = h;
        dl[(size_t)n * Kdim + k0 + tx] = __float2bfloat16(v - __bfloat162float(h));
    }
}

// ---------------- HMMA GEMM: 512 thr, 16 warps, cp.async 3-stage ------------
// 128x128 block tile, warp tile 32x32 (4m x 4n warps), K-tile 32.
// Term-outer MMA order: same-acc dependency distance = 8.
#define GSTAGE 40960
#define GEMM_DSMEM (3 * GSTAGE)
#define GEMM_NT (Kdim / 32)

template<int MODE>
__global__ void __launch_bounds__(512) mma_gemm(const float* __restrict__ bias,
                                                float* __restrict__ C, int Nc) {
    extern __shared__ char dyn[];
    const uint32_t sbase = smem_u32(dyn);

    const int tid = threadIdx.x, lane = tid & 31, wid = tid >> 5;
    const int m0 = blockIdx.y * 128, n0 = blockIdx.x * 128;
    const __nv_bfloat16* Ah = MODE ? g_xh  : g_ah;
    const __nv_bfloat16* Al = MODE ? g_xl  : g_al;
    const __nv_bfloat16* Bh = MODE ? g_wqh : g_wph;
    const __nv_bfloat16* Bl = MODE ? g_wql : g_wpl;
    const int wm = (wid >> 2) * 32, wn = (wid & 3) * 32;

    float acc[2][4][4] = {};

    const uint32_t lmr = (uint32_t)(lane & 15);
    const uint32_t lmc = (uint32_t)((lane >> 4) * 16);
    const int fr = tid >> 2, fc = tid & 3;   // fill: row (0..127), 16B chunk (0..3)

    auto fill = [&](int st, int k0) {
        uint32_t sb = sbase + st * GSTAGE;
        uint32_t o = (uint32_t)(fr * 80 + fc * 16);
        size_t ga = (size_t)(m0 + fr) * Kdim + k0 + fc * 8;
        size_t gb = (size_t)(n0 + fr) * Kdim + k0 + fc * 8;
        cp16(sb + o,          &Ah[ga]);
        cp16(sb + 10240 + o,  &Al[ga]);
        cp16(sb + 20480 + o,  &Bh[gb]);
        cp16(sb + 30720 + o,  &Bl[gb]);
    };

    fill(0, 0);  CP_COMMIT();
    fill(1, 32); CP_COMMIT();

    for (int t = 0; t < GEMM_NT; t++) {
        if (t + 2 < GEMM_NT) CP_WAIT1(); else CP_WAIT0();
        __syncthreads();
        if (t + 2 < GEMM_NT) { fill((t + 2) % 3, (t + 2) * 32); CP_COMMIT(); }

        const uint32_t sb = sbase + (t % 3) * GSTAGE;
        const uint32_t aAh = sb, aAl = sb + 10240, aBh = sb + 20480, aBl = sb + 30720;

        #pragma unroll
        for (int kt = 0; kt < 2; kt++) {
            uint32_t ah[2][4], al[2][4], bh[4][2], bl[4][2];
            #pragma unroll
            for (int mi = 0; mi < 2; mi++) {
                uint32_t ro = (wm + mi * 16 + lmr) * 80 + kt * 32 + lmc;
                ldsm4(ah[mi], aAh + ro);
                ldsm4(al[mi], aAl + ro);
            }
            #pragma unroll
            for (int g = 0; g < 2; g++) {
                uint32_t ro = (wn + g * 16 + lmr) * 80 + kt * 32 + lmc;
                uint32_t tt[4];
                ldsm4(tt, aBh + ro);
                bh[2*g][0] = tt[0]; bh[2*g][1] = tt[2];
                bh[2*g+1][0] = tt[1]; bh[2*g+1][1] = tt[3];
                ldsm4(tt, aBl + ro);
                bl[2*g][0] = tt[0]; bl[2*g][1] = tt[2];
                bl[2*g+1][0] = tt[1]; bl[2*g+1][1] = tt[3];
            }
            // term-outer: dependency distance 8
            #pragma unroll
            for (int mi = 0; mi < 2; mi++)
                #pragma unroll
                for (int ni = 0; ni < 4; ni++)
                    mma_bf16(acc[mi][ni], ah[mi], bh[ni]);
            #pragma unroll
            for (int mi = 0; mi < 2; mi++)
                #pragma unroll
                for (int ni = 0; ni < 4; ni++)
                    mma_bf16(acc[mi][ni], ah[mi], bl[ni]);
            #pragma unroll
            for (int mi = 0; mi < 2; mi++)
                #pragma unroll
                for (int ni = 0; ni < 4; ni++)
                    mma_bf16(acc[mi][ni], al[mi], bh[ni]);
        }
    }

    // epilogue
    #pragma unroll
    for (int mi = 0; mi < 2; mi++) {
        int r0 = m0 + wm + mi * 16 + (lane >> 2);
        #pragma unroll
        for (int ni = 0; ni < 4; ni++) {
            int col = n0 + wn + ni * 8 + 2 * (lane & 3);
            float b0 = bias[col], b1 = bias[col + 1];
            #pragma unroll
            for (int rr = 0; rr < 2; rr++) {
                int row = r0 + rr * 8;
                float v0 = acc[mi][ni][rr * 2 + 0] + b0;
                float v1 = acc[mi][ni][rr * 2 + 1] + b1;
                if (MODE == 0) {
                    *(float2*)&C[(size_t)row * Nc + col] = make_float2(v0, v1);
                } else {
                    int bb = row >> 11, nn = row & 2047;
                    int which = col >> 10, rem = col & 1023;
                    int hh = rem >> 6, dd = rem & 63;
                    if (which == 0) { v0 *= SCALE; v1 *= SCALE; }
                    __nv_bfloat16 h0 = __float2bfloat16(v0), h1 = __float2bfloat16(v1);
                    __nv_bfloat16 l0 = __float2bfloat16(v0 - __bfloat162float(h0));
                    __nv_bfloat16 l1 = __float2bfloat16(v1 - __bfloat162float(h1));
                    size_t idx = (((size_t)(bb * Hh + hh)) * Nseq + nn) * HD + dd;
                    __nv_bfloat16* dh = (which == 0) ? g_qh : (which == 1) ? g_kh : g_vh;
                    __nv_bfloat16* dl = (which == 0) ? g_ql : (which == 1) ? g_kl : g_vl;
                    *(__nv_bfloat162*)&dh[idx] = __nv_bfloat162(h0, h1);
                    *(__nv_bfloat162*)&dl[idx] = __nv_bfloat162(l0, l1);
                }
            }
        }
    }
}

// ---------------- flash attention: cp.async 3-stage, term-reordered ----------
// 8 warps, Q-tile 128 (Q in registers), K-tile 64.
#define FSTAGE 36864
#define FLASH_DSMEM (3 * FSTAGE + 3 * 256)
#define FLASH_NT (Nseq / 64)

__global__ void __launch_bounds__(256) flash_mma(const float* __restrict__ attn_bias) {
    extern __shared__ char dyn[];
    const uint32_t sbase = smem_u32(dyn);
    const uint32_t sbias = sbase + 3 * FSTAGE;

    const int tid = threadIdx.x, lane = tid & 31, wid = tid >> 5;
    const int b = blockIdx.z, h = blockIdx.y, q0 = blockIdx.x * 128;
    const size_t hoff = (size_t)((b * Hh + h) * Nseq) * HD;
    const __nv_bfloat16 *Qhp = g_qh + hoff, *Qlp = g_ql + hoff;
    const __nv_bfloat16 *Khp = g_kh + hoff, *Klp = g_kl + hoff;
    const __nv_bfloat16 *Vhp = g_vh + hoff, *Vlp = g_vl + hoff;
    const float* biasg = attn_bias + b * Nseq;

    const int fr = tid >> 3, fc = tid & 7;

    auto fill = [&](int st, int k0) {
        uint32_t sb = sbase + st * FSTAGE;
        #pragma unroll
        for (int half = 0; half < 2; half++) {
            int r = fr + half * 32;
            uint32_t o = (uint32_t)(r * 144 + fc * 16);
            size_t g = (size_t)(k0 + r) * HD + fc * 8;
            cp16(sb + o,             &Khp[g]);
            cp16(sb + 9216 + o,      &Klp[g]);
            cp16(sb + 18432 + o,     &Vhp[g]);
            cp16(sb + 27648 + o,     &Vlp[g]);
        }
        if (tid < 16) cp16(sbias + st * 256 + tid * 16, &biasg[k0 + tid * 4]);
    };

    uint32_t qh[4][4], ql[4][4];
    {
        int r = q0 + wid * 16 + (lane >> 2);
        int c = 2 * (lane & 3);
        #pragma unroll
        for (int kf = 0; kf < 4; kf++) {
            #pragma unroll
            for (int e = 0; e < 4; e++) {
                size_t g = (size_t)(r + (e & 1) * 8) * HD + kf * 16 + (e >> 1) * 8 + c;
                qh[kf][e] = *(const uint32_t*)&Qhp[g];
                ql[kf][e] = *(const uint32_t*)&Qlp[g];
            }
        }
    }

    fill(0, 0);  CP_COMMIT();
    fill(1, 64); CP_COMMIT();

    float O[8][4] = {};
    float mrow0 = -1e30f, mrow1 = -1e30f, lrow0 = 0.f, lrow1 = 0.f;

    for (int t = 0; t < FLASH_NT; t++) {
        if (t + 2 < FLASH_NT) CP_WAIT1(); else CP_WAIT0();
        __syncthreads();
        if (t + 2 < FLASH_NT) { fill((t + 2) % 3, (t + 2) * 64); CP_COMMIT(); }

        const uint32_t sb = sbase + (t % 3) * FSTAGE;
        const uint32_t aKh = sb, aKl = sb + 9216, aVh = sb + 18432, aVl = sb + 27648;
        const float* sB = (const float*)(dyn + 3 * FSTAGE + (t % 3) * 256);

        // ---- S = Q K^T (g processed in pairs; term-outer, distance 4) ----
        float S[8][4] = {};
        #pragma unroll
        for (int kf = 0; kf < 4; kf++) {
            #pragma unroll
            for (int gp = 0; gp < 2; gp++) {
                uint32_t bh[4][2], bl[4][2];
                #pragma unroll
                for (int gg = 0; gg < 2; gg++) {
                    int g = gp * 2 + gg;
                    uint32_t ro = (uint32_t)((g * 16 + (lane & 15)) * 144 + kf * 32 + (lane >> 4) * 16);
                    uint32_t tt[4];
                    ldsm4(tt, aKh + ro);
                    bh[2*gg][0] = tt[0]; bh[2*gg][1] = tt[2];
                    bh[2*gg+1][0] = tt[1]; bh[2*gg+1][1] = tt[3];
                    ldsm4(tt, aKl + ro);
                    bl[2*gg][0] = tt[0]; bl[2*gg][1] = tt[2];
                    bl[2*gg+1][0] = tt[1]; bl[2*gg+1][1] = tt[3];
                }
                #pragma unroll
                for (int n2 = 0; n2 < 4; n2++) mma_bf16(S[4*gp + n2], qh[kf], bh[n2]);
                #pragma unroll
                for (int n2 = 0; n2 < 4; n2++) mma_bf16(S[4*gp + n2], qh[kf], bl[n2]);
                #pragma unroll
                for (int n2 = 0; n2 < 4; n2++) mma_bf16(S[4*gp + n2], ql[kf], bh[n2]);
            }
        }

        // ---- bias + online softmax ----
        float mx0 = mrow0, mx1 = mrow1;
        #pragma unroll
        for (int nt = 0; nt < 8; nt++) {
            float2 bb = *(const float2*)&sB[nt * 8 + 2 * (lane & 3)];
            S[nt][0] += bb.x; S[nt][1] += bb.y;
            S[nt][2] += bb.x; S[nt][3] += bb.y;
            mx0 = fmaxf(mx0, fmaxf(S[nt][0], S[nt][1]));
            mx1 = fmaxf(mx1, fmaxf(S[nt][2], S[nt][3]));
        }
        mx0 = fmaxf(mx0, __shfl_xor_sync(0xffffffffu, mx0, 1));
        mx0 = fmaxf(mx0, __shfl_xor_sync(0xffffffffu, mx0, 2));
        mx1 = fmaxf(mx1, __shfl_xor_sync(0xffffffffu, mx1, 1));
        mx1 = fmaxf(mx1, __shfl_xor_sync(0xffffffffu, mx1, 2));
        float alpha0 = __expf(mrow0 - mx0), alpha1 = __expf(mrow1 - mx1);
        mrow0 = mx0; mrow1 = mx1;
        float sum0 = 0.f, sum1 = 0.f;
        #pragma unroll
        for (int nt = 0; nt < 8; nt++) {
            S[nt][0] = __expf(S[nt][0] - mx0); S[nt][1] = __expf(S[nt][1] - mx0);
            S[nt][2] = __expf(S[nt][2] - mx1); S[nt][3] = __expf(S[nt][3] - mx1);
            sum0 += S[nt][0] + S[nt][1];
            sum1 += S[nt][2] + S[nt][3];
        }
        sum0 += __shfl_xor_sync(0xffffffffu, sum0, 1);
        sum0 += __shfl_xor_sync(0xffffffffu, sum0, 2);
        sum1 += __shfl_xor_sync(0xffffffffu, sum1, 1);
        sum1 += __shfl_xor_sync(0xffffffffu, sum1, 2);
        lrow0 = lrow0 * alpha0 + sum0;
        lrow1 = lrow1 * alpha1 + sum1;
        #pragma unroll
        for (int dt = 0; dt < 8; dt++) {
            O[dt][0] *= alpha0; O[dt][1] *= alpha0;
            O[dt][2] *= alpha1; O[dt][3] *= alpha1;
        }

        // ---- P -> A-fragments (hi/lo split) ----
        uint32_t pah[4][4], pal[4][4];
        #pragma unroll
        for (int kt = 0; kt < 4; kt++) {
            #pragma unroll
            for (int half = 0; half < 2; half++) {
                int nt = 2 * kt + half;
                float p0 = S[nt][0], p1 = S[nt][1], p2 = S[nt][2], p3 = S[nt][3];
                __nv_bfloat16 h0 = __float2bfloat16(p0), h1 = __float2bfloat16(p1);
                __nv_bfloat16 h2 = __float2bfloat16(p2), h3 = __float2bfloat16(p3);
                pah[kt][half * 2 + 0] = pack_bf16(__bfloat162float(h0), __bfloat162float(h1));
                pah[kt][half * 2 + 1] = pack_bf16(__bfloat162float(h2), __bfloat162float(h3));
                pal[kt][half * 2 + 0] = pack_bf16(p0 - __bfloat162float(h0), p1 - __bfloat162float(h1));
                pal[kt][half * 2 + 1] = pack_bf16(p2 - __bfloat162float(h2), p3 - __bfloat162float(h3));
            }
        }

        // ---- O += P V (g pairs, term-outer, distance 4) ----
        #pragma unroll
        for (int kt = 0; kt < 4; kt++) {
            #pragma unroll
            for (int gp = 0; gp < 2; gp++) {
                uint32_t vh[4][2], vl[4][2];
                #pragma unroll
                for (int gg = 0; gg < 2; gg++) {
                    int g = gp * 2 + gg;
                    uint32_t ro = (uint32_t)((kt * 16 + (lane & 7) + 8 * ((lane >> 3) & 1)) * 144
                                             + g * 32 + (lane >> 4) * 16);
                    uint32_t tt[4];
                    ldsm4t(tt, aVh + ro);
                    vh[2*gg][0] = tt[0]; vh[2*gg][1] = tt[1];
                    vh[2*gg+1][0] = tt[2]; vh[2*gg+1][1] = tt[3];
                    ldsm4t(tt, aVl + ro);
                    vl[2*gg][0] = tt[0]; vl[2*gg][1] = tt[1];
                    vl[2*gg+1][0] = tt[2]; vl[2*gg+1][1] = tt[3];
                }
                #pragma unroll
                for (int n2 = 0; n2 < 4; n2++) mma_bf16(O[4*gp + n2], pah[kt], vh[n2]);
                #pragma unroll
                for (int n2 = 0; n2 < 4; n2++) mma_bf16(O[4*gp + n2], pah[kt], vl[n2]);
                #pragma unroll
                for (int n2 = 0; n2 < 4; n2++) mma_bf16(O[4*gp + n2], pal[kt], vh[n2]);
            }
        }
    }

    // ---- epilogue ----
    float inv0 = 1.f / lrow0, inv1 = 1.f / lrow1;
    int r0 = q0 + wid * 16 + (lane >> 2);
    #pragma unroll
    for (int dt = 0; dt < 8; dt++) {
        int col = h * HD + dt * 8 + 2 * (lane & 3);
        float v00 = O[dt][0] * inv0, v01 = O[dt][1] * inv0;
        float v10 = O[dt][2] * inv1, v11 = O[dt][3] * inv1;
        size_t i0 = (size_t)(b * Nseq + r0) * Dm + col;
        size_t i1 = (size_t)(b * Nseq + r0 + 8) * Dm + col;
        __nv_bfloat16 h00 = __float2bfloat16(v00), h01 = __float2bfloat16(v01);
        __nv_bfloat16 h10 = __float2bfloat16(v10), h11 = __float2bfloat16(v11);
        *(__nv_bfloat162*)&g_ah[i0] = __nv_bfloat162(h00, h01);
        *(__nv_bfloat162*)&g_ah[i1] = __nv_bfloat162(h10, h11);
        *(__nv_bfloat162*)&g_al[i0] = __nv_bfloat162(
            __float2bfloat16(v00 - __bfloat162float(h00)),
            __float2bfloat16(v01 - __bfloat162float(h01)));
        *(__nv_bfloat162*)&g_al[i1] = __nv_bfloat162(
            __float2bfloat16(v10 - __bfloat162float(h10)),
            __float2bfloat16(v11 - __bfloat162float(h11)));
    }
}

// ---------------- launch -----------------------------------------------------
extern "C" void kernel_launch(void* const* d_in, const int* in_sizes, int n_in,
                              void* d_out, int out_size)
{
    const float* x         = (const float*)d_in[0];
    const float* attn_bias = (const float*)d_in[1];
    const float* w_qkv     = (const float*)d_in[2];
    const float* b_qkv     = (const float*)d_in[3];
    const float* w_proj    = (const float*)d_in[4];
    const float* b_proj    = (const float*)d_in[5];
    float* out = (float*)d_out;

    cudaFuncSetAttribute(mma_gemm<1>, cudaFuncAttributeMaxDynamicSharedMemorySize, GEMM_DSMEM);
    cudaFuncSetAttribute(mma_gemm<0>, cudaFuncAttributeMaxDynamicSharedMemorySize, GEMM_DSMEM);
    cudaFuncSetAttribute(flash_mma,   cudaFuncAttributeMaxDynamicSharedMemorySize, FLASH_DSMEM);

    conv_x_kernel<<<(Bd * Nseq * Dm) / (256 * 4), 256>>>(x);
    convT_kernel<0><<<dim3(3 * Dm / 32, Kdim / 32), 256>>>(w_qkv, 3 * Dm);
    convT_kernel<1><<<dim3(Dm / 32, Kdim / 32), 256>>>(w_proj, Dm);

    mma_gemm<1><<<dim3(3 * Dm / 128, (Bd * Nseq) / 128), 512, GEMM_DSMEM>>>(b_qkv, nullptr, 3 * Dm);

    flash_mma<<<dim3(Nseq / 128, Hh, Bd), 256, FLASH_DSMEM>>>(attn_bias);

    mma_gemm<0><<<dim3(Dm / 128, (Bd * Nseq) / 128), 512, GEMM_DSMEM>>>(b_proj, out, Dm);
}

// round 10
// speedup vs baseline: 2.7063x; 2.7040x over previous
#include <cuda_runtime.h>
#include <cuda_fp16.h>
#include <stdint.h>

// Problem constants
#define Bd   2
#define Nseq 2048
#define Dm   1024
#define Hh   16
#define HD   64
#define SCALE 0.125f
#define Kdim 1024

// ---------------- device scratch (no allocations allowed) -------------------
__device__ __half g_x[Bd*Nseq*Dm];          // x fp16
__device__ __half g_wq[3*Dm*Kdim];          // w_qkv^T fp16 [3072,1024]
__device__ __half g_wp[Dm*Kdim];            // w_proj^T fp16 [1024,1024]
__device__ __half g_q[Bd*Hh*Nseq*HD];       // q*scale fp16 [B,H,N,64]
__device__ __half g_k[Bd*Hh*Nseq*HD];
__device__ __half g_v[Bd*Hh*Nseq*HD];
__device__ __half g_a[Bd*Nseq*Dm];          // attention out fp16

// ---------------- helpers ----------------------------------------------------
__device__ __forceinline__ uint32_t smem_u32(const void* p) {
    return (uint32_t)__cvta_generic_to_shared(p);
}
__device__ __forceinline__ void mma_f16(float (&d)[4], const uint32_t (&a)[4],
                                        const uint32_t (&b)[2]) {
    asm volatile(
        "mma.sync.aligned.m16n8k16.row.col.f32.f16.f16.f32 "
        "{%0,%1,%2,%3}, {%4,%5,%6,%7}, {%8,%9}, {%0,%1,%2,%3};"
        : "+f"(d[0]), "+f"(d[1]), "+f"(d[2]), "+f"(d[3])
        : "r"(a[0]), "r"(a[1]), "r"(a[2]), "r"(a[3]), "r"(b[0]), "r"(b[1]));
}
__device__ __forceinline__ void ldsm4(uint32_t (&r)[4], uint32_t addr) {
    asm volatile("ldmatrix.sync.aligned.m8n8.x4.shared.b16 {%0,%1,%2,%3}, [%4];"
        : "=r"(r[0]), "=r"(r[1]), "=r"(r[2]), "=r"(r[3]) : "r"(addr));
}
__device__ __forceinline__ void ldsm4t(uint32_t (&r)[4], uint32_t addr) {
    asm volatile("ldmatrix.sync.aligned.m8n8.x4.trans.shared.b16 {%0,%1,%2,%3}, [%4];"
        : "=r"(r[0]), "=r"(r[1]), "=r"(r[2]), "=r"(r[3]) : "r"(addr));
}
__device__ __forceinline__ uint32_t pack_f16(float lo, float hi) {
    __half2 h = __floats2half2_rn(lo, hi);
    return *(uint32_t*)&h;
}
__device__ __forceinline__ void cp16(uint32_t s, const void* g) {
    asm volatile("cp.async.cg.shared.global [%0], [%1], 16;" :: "r"(s), "l"(g));
}
#define CP_COMMIT() asm volatile("cp.async.commit_group;" ::: "memory")
#define CP_WAIT1()  asm volatile("cp.async.wait_group 1;" ::: "memory")
#define CP_WAIT0()  asm volatile("cp.async.wait_group 0;" ::: "memory")

// ---------------- convert pre-passes -----------------------------------------
__global__ void __launch_bounds__(256) conv_x_kernel(const float* __restrict__ x) {
    int i4 = (blockIdx.x * 256 + threadIdx.x) * 4;
    if (i4 >= Bd * Nseq * Dm) return;
    float4 v = *(const float4*)&x[i4];
    *(__half2*)&g_x[i4]     = __floats2half2_rn(v.x, v.y);
    *(__half2*)&g_x[i4 + 2] = __floats2half2_rn(v.z, v.w);
}

template<int WHICH>  // 0: qkv, 1: proj
__global__ void __launch_bounds__(256) convT_kernel(const float* __restrict__ w, int N) {
    __shared__ float t[32][33];
    int tx = threadIdx.x & 31, ty = threadIdx.x >> 5;   // 32 x 8
    int n0 = blockIdx.x * 32, k0 = blockIdx.y * 32;
    #pragma unroll
    for (int i = 0; i < 4; i++) {
        int k = k0 + ty + i * 8;
        t[ty + i * 8][tx] = w[(size_t)k * N + n0 + tx];
    }
    __syncthreads();
    __half* dst = WHICH ? g_wp : g_wq;
    #pragma unroll
    for (int i = 0; i < 4; i++) {
        int n = n0 + ty + i * 8;
        dst[(size_t)n * Kdim + k0 + tx] = __float2half_rn(t[tx][ty + i * 8]);
    }
}

// ---------------- HMMA GEMM: fp16 single, 512 thr, cp.async 3-stage ----------
// 128x128 block tile, warp tile 32x32 (4m x 4n warps), K-tile 32 (fp16: 64B rows).
#define GSTAGE 20480
#define GEMM_DSMEM (3 * GSTAGE)
#define GEMM_NT (Kdim / 32)

template<int MODE>
__global__ void __launch_bounds__(512) mma_gemm(const float* __restrict__ bias,
                                                float* __restrict__ C, int Nc) {
    extern __shared__ char dyn[];
    const uint32_t sbase = smem_u32(dyn);

    const int tid = threadIdx.x, lane = tid & 31, wid = tid >> 5;
    const int m0 = blockIdx.y * 128, n0 = blockIdx.x * 128;
    const __half* A = MODE ? g_x : g_a;
    const __half* B = MODE ? g_wq : g_wp;
    const int wm = (wid >> 2) * 32, wn = (wid & 3) * 32;

    float acc[2][4][4] = {};

    const uint32_t lmr = (uint32_t)(lane & 15);
    const uint32_t lmc = (uint32_t)((lane >> 4) * 16);
    const int fr = tid >> 2, fc = tid & 3;   // fill: row (0..127), 16B chunk (0..3)

    auto fill = [&](int st, int k0) {
        uint32_t sb = sbase + st * GSTAGE;
        uint32_t o = (uint32_t)(fr * 80 + fc * 16);
        cp16(sb + o,          &A[(size_t)(m0 + fr) * Kdim + k0 + fc * 8]);
        cp16(sb + 10240 + o,  &B[(size_t)(n0 + fr) * Kdim + k0 + fc * 8]);
    };

    fill(0, 0);  CP_COMMIT();
    fill(1, 32); CP_COMMIT();

    for (int t = 0; t < GEMM_NT; t++) {
        if (t + 2 < GEMM_NT) CP_WAIT1(); else CP_WAIT0();
        __syncthreads();
        if (t + 2 < GEMM_NT) { fill((t + 2) % 3, (t + 2) * 32); CP_COMMIT(); }

        const uint32_t sb = sbase + (t % 3) * GSTAGE;
        const uint32_t aA = sb, aB = sb + 10240;

        #pragma unroll
        for (int kt = 0; kt < 2; kt++) {
            uint32_t a[2][4], b[4][2];
            #pragma unroll
            for (int mi = 0; mi < 2; mi++) {
                uint32_t ro = (wm + mi * 16 + lmr) * 80 + kt * 32 + lmc;
                ldsm4(a[mi], aA + ro);
            }
            #pragma unroll
            for (int g = 0; g < 2; g++) {
                uint32_t ro = (wn + g * 16 + lmr) * 80 + kt * 32 + lmc;
                uint32_t tt[4];
                ldsm4(tt, aB + ro);
                b[2*g][0] = tt[0]; b[2*g][1] = tt[2];
                b[2*g+1][0] = tt[1]; b[2*g+1][1] = tt[3];
            }
            #pragma unroll
            for (int mi = 0; mi < 2; mi++)
                #pragma unroll
                for (int ni = 0; ni < 4; ni++)
                    mma_f16(acc[mi][ni], a[mi], b[ni]);
        }
    }

    // epilogue
    #pragma unroll
    for (int mi = 0; mi < 2; mi++) {
        int r0 = m0 + wm + mi * 16 + (lane >> 2);
        #pragma unroll
        for (int ni = 0; ni < 4; ni++) {
            int col = n0 + wn + ni * 8 + 2 * (lane & 3);
            float b0 = bias[col], b1 = bias[col + 1];
            #pragma unroll
            for (int rr = 0; rr < 2; rr++) {
                int row = r0 + rr * 8;
                float v0 = acc[mi][ni][rr * 2 + 0] + b0;
                float v1 = acc[mi][ni][rr * 2 + 1] + b1;
                if (MODE == 0) {
                    *(float2*)&C[(size_t)row * Nc + col] = make_float2(v0, v1);
                } else {
                    int bb = row >> 11, nn = row & 2047;
                    int which = col >> 10, rem = col & 1023;
                    int hh = rem >> 6, dd = rem & 63;
                    if (which == 0) { v0 *= SCALE; v1 *= SCALE; }
                    size_t idx = (((size_t)(bb * Hh + hh)) * Nseq + nn) * HD + dd;
                    __half* dst = (which == 0) ? g_q : (which == 1) ? g_k : g_v;
                    *(__half2*)&dst[idx] = __floats2half2_rn(v0, v1);
                }
            }
        }
    }
}

// ---------------- flash attention: fp16 single, cp.async 3-stage -------------
// 8 warps, Q-tile 128 (Q in registers), K-tile 64. Rows 128B fp16, pitch 144B.
#define FSTAGE 18432
#define FLASH_DSMEM (3 * FSTAGE + 3 * 256)
#define FLASH_NT (Nseq / 64)

__global__ void __launch_bounds__(256) flash_mma(const float* __restrict__ attn_bias) {
    extern __shared__ char dyn[];
    const uint32_t sbase = smem_u32(dyn);
    const uint32_t sbias = sbase + 3 * FSTAGE;

    const int tid = threadIdx.x, lane = tid & 31, wid = tid >> 5;
    const int b = blockIdx.z, h = blockIdx.y, q0 = blockIdx.x * 128;
    const size_t hoff = (size_t)((b * Hh + h) * Nseq) * HD;
    const __half *Qp = g_q + hoff, *Kp = g_k + hoff, *Vp = g_v + hoff;
    const float* biasg = attn_bias + b * Nseq;

    const int fr = tid >> 3, fc = tid & 7;   // row base (0..31), 16B chunk (0..7)

    auto fill = [&](int st, int k0) {
        uint32_t sb = sbase + st * FSTAGE;
        #pragma unroll
        for (int half = 0; half < 2; half++) {
            int r = fr + half * 32;
            uint32_t o = (uint32_t)(r * 144 + fc * 16);
            size_t g = (size_t)(k0 + r) * HD + fc * 8;
            cp16(sb + o,        &Kp[g]);
            cp16(sb + 9216 + o, &Vp[g]);
        }
        if (tid < 16) cp16(sbias + st * 256 + tid * 16, &biasg[k0 + tid * 4]);
    };

    // ---- Q A-fragments directly from gmem ----
    uint32_t qf[4][4];
    {
        int r = q0 + wid * 16 + (lane >> 2);
        int c = 2 * (lane & 3);
        #pragma unroll
        for (int kf = 0; kf < 4; kf++) {
            #pragma unroll
            for (int e = 0; e < 4; e++) {
                size_t g = (size_t)(r + (e & 1) * 8) * HD + kf * 16 + (e >> 1) * 8 + c;
                qf[kf][e] = *(const uint32_t*)&Qp[g];
            }
        }
    }

    fill(0, 0);  CP_COMMIT();
    fill(1, 64); CP_COMMIT();

    float O[8][4] = {};
    float mrow0 = -1e30f, mrow1 = -1e30f, lrow0 = 0.f, lrow1 = 0.f;

    for (int t = 0; t < FLASH_NT; t++) {
        if (t + 2 < FLASH_NT) CP_WAIT1(); else CP_WAIT0();
        __syncthreads();
        if (t + 2 < FLASH_NT) { fill((t + 2) % 3, (t + 2) * 64); CP_COMMIT(); }

        const uint32_t sb = sbase + (t % 3) * FSTAGE;
        const uint32_t aK = sb, aV = sb + 9216;
        const float* sB = (const float*)(dyn + 3 * FSTAGE + (t % 3) * 256);

        // ---- S = Q K^T ----
        float S[8][4] = {};
        #pragma unroll
        for (int kf = 0; kf < 4; kf++) {
            #pragma unroll
            for (int g = 0; g < 4; g++) {
                uint32_t ro = (uint32_t)((g * 16 + (lane & 15)) * 144 + kf * 32 + (lane >> 4) * 16);
                uint32_t tt[4], b0[2], b1[2];
                ldsm4(tt, aK + ro);
                b0[0] = tt[0]; b0[1] = tt[2]; b1[0] = tt[1]; b1[1] = tt[3];
                mma_f16(S[2*g],   qf[kf], b0);
                mma_f16(S[2*g+1], qf[kf], b1);
            }
        }

        // ---- bias + online softmax ----
        float mx0 = mrow0, mx1 = mrow1;
        #pragma unroll
        for (int nt = 0; nt < 8; nt++) {
            float2 bb = *(const float2*)&sB[nt * 8 + 2 * (lane & 3)];
            S[nt][0] += bb.x; S[nt][1] += bb.y;
            S[nt][2] += bb.x; S[nt][3] += bb.y;
            mx0 = fmaxf(mx0, fmaxf(S[nt][0], S[nt][1]));
            mx1 = fmaxf(mx1, fmaxf(S[nt][2], S[nt][3]));
        }
        mx0 = fmaxf(mx0, __shfl_xor_sync(0xffffffffu, mx0, 1));
        mx0 = fmaxf(mx0, __shfl_xor_sync(0xffffffffu, mx0, 2));
        mx1 = fmaxf(mx1, __shfl_xor_sync(0xffffffffu, mx1, 1));
        mx1 = fmaxf(mx1, __shfl_xor_sync(0xffffffffu, mx1, 2));
        float alpha0 = __expf(mrow0 - mx0), alpha1 = __expf(mrow1 - mx1);
        mrow0 = mx0; mrow1 = mx1;
        float sum0 = 0.f, sum1 = 0.f;
        #pragma unroll
        for (int nt = 0; nt < 8; nt++) {
            S[nt][0] = __expf(S[nt][0] - mx0); S[nt][1] = __expf(S[nt][1] - mx0);
            S[nt][2] = __expf(S[nt][2] - mx1); S[nt][3] = __expf(S[nt][3] - mx1);
            sum0 += S[nt][0] + S[nt][1];
            sum1 += S[nt][2] + S[nt][3];
        }
        sum0 += __shfl_xor_sync(0xffffffffu, sum0, 1);
        sum0 += __shfl_xor_sync(0xffffffffu, sum0, 2);
        sum1 += __shfl_xor_sync(0xffffffffu, sum1, 1);
        sum1 += __shfl_xor_sync(0xffffffffu, sum1, 2);
        lrow0 = lrow0 * alpha0 + sum0;
        lrow1 = lrow1 * alpha1 + sum1;
        #pragma unroll
        for (int dt = 0; dt < 8; dt++) {
            O[dt][0] *= alpha0; O[dt][1] *= alpha0;
            O[dt][2] *= alpha1; O[dt][3] *= alpha1;
        }

        // ---- P -> fp16 A-fragments ----
        uint32_t pf[4][4];
        #pragma unroll
        for (int kt = 0; kt < 4; kt++) {
            #pragma unroll
            for (int half = 0; half < 2; half++) {
                int nt = 2 * kt + half;
                pf[kt][half * 2 + 0] = pack_f16(S[nt][0], S[nt][1]);
                pf[kt][half * 2 + 1] = pack_f16(S[nt][2], S[nt][3]);
            }
        }

        // ---- O += P V ----
        #pragma unroll
        for (int kt = 0; kt < 4; kt++) {
            #pragma unroll
            for (int g = 0; g < 4; g++) {
                uint32_t ro = (uint32_t)((kt * 16 + (lane & 7) + 8 * ((lane >> 3) & 1)) * 144
                                         + g * 32 + (lane >> 4) * 16);
                uint32_t tt[4], v0[2], v1[2];
                ldsm4t(tt, aV + ro);
                v0[0] = tt[0]; v0[1] = tt[1]; v1[0] = tt[2]; v1[1] = tt[3];
                mma_f16(O[2*g],   pf[kt], v0);
                mma_f16(O[2*g+1], pf[kt], v1);
            }
        }
    }

    // ---- epilogue: normalize, write fp16 attention output ----
    float inv0 = 1.f / lrow0, inv1 = 1.f / lrow1;
    int r0 = q0 + wid * 16 + (lane >> 2);
    #pragma unroll
    for (int dt = 0; dt < 8; dt++) {
        int col = h * HD + dt * 8 + 2 * (lane & 3);
        size_t i0 = (size_t)(b * Nseq + r0) * Dm + col;
        size_t i1 = (size_t)(b * Nseq + r0 + 8) * Dm + col;
        *(__half2*)&g_a[i0] = __floats2half2_rn(O[dt][0] * inv0, O[dt][1] * inv0);
        *(__half2*)&g_a[i1] = __floats2half2_rn(O[dt][2] * inv1, O[dt][3] * inv1);
    }
}

// ---------------- launch -----------------------------------------------------
extern "C" void kernel_launch(void* const* d_in, const int* in_sizes, int n_in,
                              void* d_out, int out_size)
{
    const float* x         = (const float*)d_in[0];
    const float* attn_bias = (const float*)d_in[1];
    const float* w_qkv     = (const float*)d_in[2];
    const float* b_qkv     = (const float*)d_in[3];
    const float* w_proj    = (const float*)d_in[4];
    const float* b_proj    = (const float*)d_in[5];
    float* out = (float*)d_out;

    cudaFuncSetAttribute(mma_gemm<1>, cudaFuncAttributeMaxDynamicSharedMemorySize, GEMM_DSMEM);
    cudaFuncSetAttribute(mma_gemm<0>, cudaFuncAttributeMaxDynamicSharedMemorySize, GEMM_DSMEM);
    cudaFuncSetAttribute(flash_mma,   cudaFuncAttributeMaxDynamicSharedMemorySize, FLASH_DSMEM);

    conv_x_kernel<<<(Bd * Nseq * Dm) / (256 * 4), 256>>>(x);
    convT_kernel<0><<<dim3(3 * Dm / 32, Kdim / 32), 256>>>(w_qkv, 3 * Dm);
    convT_kernel<1><<<dim3(Dm / 32, Kdim / 32), 256>>>(w_proj, Dm);

    mma_gemm<1><<<dim3(3 * Dm / 128, (Bd * Nseq) / 128), 512, GEMM_DSMEM>>>(b_qkv, nullptr, 3 * Dm);

    flash_mma<<<dim3(Nseq / 128, Hh, Bd), 256, FLASH_DSMEM>>>(attn_bias);

    mma_gemm<0><<<dim3(Dm / 128, (Bd * Nseq) / 128), 512, GEMM_DSMEM>>>(b_proj, out, Dm);
}